// round 10
// baseline (speedup 1.0000x reference)
#include <cuda_runtime.h>
#include <cuda_fp16.h>
#include <cstdint>

#define N_NODES 20000
#define N_EDGES 160000
#define DIM 32
#define EFD 95
#define EH 64
#define NG 64
#define ZCOLS 2048      // EH * DIM
#define BN_EPS 1e-5f
#define EPB 64          // edges per fused block
#define EAS 98          // padded ea row stride (halves)
#define HSS 68          // padded hs row stride (floats)

// ---------------- scratch (device globals) ----------------
__device__ __align__(16) __half g_Zh[(size_t)N_NODES * ZCOLS];  // 82 MB  [n][kb][o][r]
__device__ float  g_Zb[N_NODES * DIM];
__device__ float  g_agg[N_NODES * DIM];
__device__ float  g_x1[N_NODES * DIM];
__device__ float  g_pool[NG * DIM];

// ---------------- zero kernels ----------------
__global__ void k_zero_agg_pool() {
    int i = blockIdx.x * blockDim.x + threadIdx.x;
    if (i < NG * DIM) g_pool[i] = 0.f;
    if (i < N_NODES * DIM) g_agg[i] = 0.f;
}
__global__ void k_zero_agg() {
    int i = blockIdx.x * blockDim.x + threadIdx.x;
    if (i < N_NODES * DIM) g_agg[i] = 0.f;
}

// ---------------- K2: Zh[n][kb][o][r] (round-3 core) + Zb fold on kb==0 ---
__global__ void __launch_bounds__(256) k_zgemm(const float* __restrict__ X,
                                               const float* __restrict__ W2,
                                               const float* __restrict__ b2) {
    __shared__ float Xs[32 * DIM];      // 4 KB
    __shared__ float Bs[8 * 32 * 32];   // 32 KB, Bs[r*1024 + i*32 + o]
    __shared__ float b2s[1024];         // 4 KB (kb==0 only)
    int t = threadIdx.x;
    int kb = blockIdx.x;
    int n0 = blockIdx.y * 32;

    for (int i = t; i < 32 * DIM; i += 256)
        Xs[i] = X[(size_t)n0 * DIM + i];
    const float* w2src = W2 + (size_t)kb * 8192;
#pragma unroll
    for (int i = 0; i < 8192; i += 256)
        Bs[i + t] = w2src[i + t];
    if (kb == 0)
        for (int i = t; i < 1024; i += 256) b2s[i] = b2[i];
    __syncthreads();

    int o = t & 31, trow = t >> 5;
    float acc[4][8] = {};
#pragma unroll
    for (int i = 0; i < DIM; i++) {
        float b[8];
#pragma unroll
        for (int r = 0; r < 8; r++) b[r] = Bs[r * 1024 + i * 32 + o];
#pragma unroll
        for (int rr = 0; rr < 4; rr++) {
            float a = Xs[(trow * 4 + rr) * DIM + i];
#pragma unroll
            for (int r = 0; r < 8; r++)
                acc[rr][r] = fmaf(a, b[r], acc[rr][r]);
        }
    }
#pragma unroll
    for (int rr = 0; rr < 4; rr++) {
        int n = n0 + trow * 4 + rr;
        __half2 p0 = __floats2half2_rn(acc[rr][0], acc[rr][1]);
        __half2 p1 = __floats2half2_rn(acc[rr][2], acc[rr][3]);
        __half2 p2 = __floats2half2_rn(acc[rr][4], acc[rr][5]);
        __half2 p3 = __floats2half2_rn(acc[rr][6], acc[rr][7]);
        uint4 pk = make_uint4(*(uint32_t*)&p0, *(uint32_t*)&p1,
                              *(uint32_t*)&p2, *(uint32_t*)&p3);
        *(uint4*)&g_Zh[(size_t)n * ZCOLS + kb * 256 + o * 8] = pk;
    }
    // ---- Zb fold (kb==0 blocks only): Zb[n,o] = sum_i X[n,i]*b2[i*32+o] ----
    if (kb == 0) {
        float v[4] = {};
#pragma unroll
        for (int i = 0; i < DIM; i++) {
            float bb = b2s[i * 32 + o];
#pragma unroll
            for (int rr = 0; rr < 4; rr++)
                v[rr] = fmaf(Xs[(trow * 4 + rr) * DIM + i], bb, v[rr]);
        }
#pragma unroll
        for (int rr = 0; rr < 4; rr++)
            g_Zb[(n0 + trow * 4 + rr) * DIM + o] = v[rr];
    }
}

// ---------------- K3: FUSED edge MLP + scatter (round-8, known 134us) -----
__global__ void __launch_bounds__(256) k_edge_fused(const float* __restrict__ ea,
                                                    const float* __restrict__ W1,
                                                    const float* __restrict__ b1,
                                                    const int* __restrict__ esrc,
                                                    const int* __restrict__ edst) {
    __shared__ __half W1h[EFD * EH];        // 12160 B, [k][j]
    __shared__ __half eash[EPB * EAS];      // 12544 B, [el][k], stride 98
    __shared__ float  hs[EPB][HSS];         // 17408 B
    int t = threadIdx.x;
    int e0 = blockIdx.x * EPB;

    for (int i = t; i < EFD * EH; i += 256) W1h[i] = __float2half(W1[i]);
    for (int i = t; i < EPB * EFD; i += 256) {
        int el = i / EFD, k = i - el * EFD;
        eash[el * EAS + k] = __float2half(ea[(size_t)e0 * EFD + i]);
    }
    __syncthreads();

    int lane = t & 31;
    int jg = t >> 5;
    float bj[8];
#pragma unroll
    for (int j = 0; j < 8; j++) bj[j] = b1[jg * 8 + j];

#pragma unroll
    for (int pass = 0; pass < 2; pass++) {
        int el = pass * 32 + lane;
        float acc[8];
#pragma unroll
        for (int j = 0; j < 8; j++) acc[j] = bj[j];

        const __half* ear = &eash[el * EAS];
        const __half* wr = &W1h[jg * 8];
#pragma unroll 2
        for (int k = 0; k < EFD - 1; k += 2) {
            __half2 ah = *(const __half2*)(ear + k);
            float2 af = __half22float2(ah);
            uint4 wv0 = *(const uint4*)(wr + k * EH);
            uint4 wv1 = *(const uint4*)(wr + (k + 1) * EH);
            float2 w00 = __half22float2(*(__half2*)&wv0.x);
            float2 w01 = __half22float2(*(__half2*)&wv0.y);
            float2 w02 = __half22float2(*(__half2*)&wv0.z);
            float2 w03 = __half22float2(*(__half2*)&wv0.w);
            float2 w10 = __half22float2(*(__half2*)&wv1.x);
            float2 w11 = __half22float2(*(__half2*)&wv1.y);
            float2 w12 = __half22float2(*(__half2*)&wv1.z);
            float2 w13 = __half22float2(*(__half2*)&wv1.w);
            acc[0] = fmaf(af.x, w00.x, acc[0]);
            acc[1] = fmaf(af.x, w00.y, acc[1]);
            acc[2] = fmaf(af.x, w01.x, acc[2]);
            acc[3] = fmaf(af.x, w01.y, acc[3]);
            acc[4] = fmaf(af.x, w02.x, acc[4]);
            acc[5] = fmaf(af.x, w02.y, acc[5]);
            acc[6] = fmaf(af.x, w03.x, acc[6]);
            acc[7] = fmaf(af.x, w03.y, acc[7]);
            acc[0] = fmaf(af.y, w10.x, acc[0]);
            acc[1] = fmaf(af.y, w10.y, acc[1]);
            acc[2] = fmaf(af.y, w11.x, acc[2]);
            acc[3] = fmaf(af.y, w11.y, acc[3]);
            acc[4] = fmaf(af.y, w12.x, acc[4]);
            acc[5] = fmaf(af.y, w12.y, acc[5]);
            acc[6] = fmaf(af.y, w13.x, acc[6]);
            acc[7] = fmaf(af.y, w13.y, acc[7]);
        }
        {
            int k = EFD - 1;
            float a = __half2float(ear[k]);
            uint4 wv0 = *(const uint4*)(wr + k * EH);
            float2 w00 = __half22float2(*(__half2*)&wv0.x);
            float2 w01 = __half22float2(*(__half2*)&wv0.y);
            float2 w02 = __half22float2(*(__half2*)&wv0.z);
            float2 w03 = __half22float2(*(__half2*)&wv0.w);
            acc[0] = fmaf(a, w00.x, acc[0]);
            acc[1] = fmaf(a, w00.y, acc[1]);
            acc[2] = fmaf(a, w01.x, acc[2]);
            acc[3] = fmaf(a, w01.y, acc[3]);
            acc[4] = fmaf(a, w02.x, acc[4]);
            acc[5] = fmaf(a, w02.y, acc[5]);
            acc[6] = fmaf(a, w03.x, acc[6]);
            acc[7] = fmaf(a, w03.y, acc[7]);
        }
        float4 r0 = make_float4(fmaxf(acc[0], 0.f), fmaxf(acc[1], 0.f),
                                fmaxf(acc[2], 0.f), fmaxf(acc[3], 0.f));
        float4 r1 = make_float4(fmaxf(acc[4], 0.f), fmaxf(acc[5], 0.f),
                                fmaxf(acc[6], 0.f), fmaxf(acc[7], 0.f));
        *(float4*)&hs[el][jg * 8] = r0;
        *(float4*)&hs[el][jg * 8 + 4] = r1;
    }
    __syncthreads();

    int wid = t >> 5;
#pragma unroll
    for (int rnd = 0; rnd < 8; rnd++) {
        int eloc = rnd * 8 + wid;
        int e = e0 + eloc;
        int s = esrc[e], d = edst[e];
        const __half* zr = g_Zh + (size_t)s * ZCOLS + lane * 8;
        const float* hr = hs[eloc];
        float msg0 = g_Zb[s * DIM + lane];
        float msg1 = 0.f;
#pragma unroll
        for (int kb = 0; kb < 8; kb += 2) {
            uint4 v0 = __ldg((const uint4*)(zr + kb * 256));
            uint4 v1 = __ldg((const uint4*)(zr + (kb + 1) * 256));
            float4 h0 = *(const float4*)&hr[kb * 8];
            float4 h1 = *(const float4*)&hr[kb * 8 + 4];
            float4 h2 = *(const float4*)&hr[kb * 8 + 8];
            float4 h3 = *(const float4*)&hr[kb * 8 + 12];
            float2 a0 = __half22float2(*(__half2*)&v0.x);
            float2 a1 = __half22float2(*(__half2*)&v0.y);
            float2 a2 = __half22float2(*(__half2*)&v0.z);
            float2 a3 = __half22float2(*(__half2*)&v0.w);
            float2 b0 = __half22float2(*(__half2*)&v1.x);
            float2 b1 = __half22float2(*(__half2*)&v1.y);
            float2 b2 = __half22float2(*(__half2*)&v1.z);
            float2 b3 = __half22float2(*(__half2*)&v1.w);
            msg0 = fmaf(h0.x, a0.x, msg0);
            msg1 = fmaf(h0.y, a0.y, msg1);
            msg0 = fmaf(h0.z, a1.x, msg0);
            msg1 = fmaf(h0.w, a1.y, msg1);
            msg0 = fmaf(h1.x, a2.x, msg0);
            msg1 = fmaf(h1.y, a2.y, msg1);
            msg0 = fmaf(h1.z, a3.x, msg0);
            msg1 = fmaf(h1.w, a3.y, msg1);
            msg0 = fmaf(h2.x, b0.x, msg0);
            msg1 = fmaf(h2.y, b0.y, msg1);
            msg0 = fmaf(h2.z, b1.x, msg0);
            msg1 = fmaf(h2.w, b1.y, msg1);
            msg0 = fmaf(h3.x, b2.x, msg0);
            msg1 = fmaf(h3.y, b2.y, msg1);
            msg0 = fmaf(h3.z, b3.x, msg0);
            msg1 = fmaf(h3.w, b3.y, msg1);
        }
        atomicAdd(&g_agg[d * DIM + lane], msg0 + msg1);
    }
}

// ---------------- K4: node update ----------------
template <bool POOL>
__global__ void k_node_update(const float* __restrict__ xin,
                              const float* __restrict__ root,
                              const float* __restrict__ bias,
                              const float* __restrict__ bng,
                              const float* __restrict__ bnb,
                              const float* __restrict__ bnrm,
                              const float* __restrict__ bnrv,
                              float* __restrict__ xout,
                              const int* __restrict__ batch) {
    __shared__ float Rs[DIM * DIM];
    int t = threadIdx.x;
    for (int i = t; i < DIM * DIM; i += 256) Rs[i] = root[i];
    __syncthreads();
    int n = blockIdx.x * 8 + (t >> 5);
    int o = t & 31;
    const float* xr = xin + (size_t)n * DIM;
    float v = g_agg[n * DIM + o] + bias[o];
#pragma unroll
    for (int i = 0; i < DIM; i++) v = fmaf(xr[i], Rs[i * DIM + o], v);
    v = (v - bnrm[o]) * rsqrtf(bnrv[o] + BN_EPS) * bng[o] + bnb[o];
    v = fmaxf(v, 0.f);
    if (POOL) {
        int b = batch[n];
        atomicMax((int*)&g_pool[b * DIM + o], __float_as_int(v));
    } else {
        xout[n * DIM + o] = v;
    }
}

// ---------------- K6: head ----------------
__global__ void k_head(const float* __restrict__ l1W, const float* __restrict__ l1b,
                       const float* __restrict__ l2W, const float* __restrict__ l2b,
                       float* __restrict__ out) {
    int g = threadIdx.x;
    const float* pr = &g_pool[g * DIM];
    float tbuf[DIM];
#pragma unroll
    for (int j = 0; j < DIM; j++) {
        float v = l1b[j];
#pragma unroll
        for (int i = 0; i < DIM; i++) v = fmaf(pr[i], l1W[i * DIM + j], v);
        tbuf[j] = fmaxf(v, 0.f);
    }
#pragma unroll
    for (int c = 0; c < 2; c++) {
        float v = l2b[c];
#pragma unroll
        for (int j = 0; j < DIM; j++) v = fmaf(tbuf[j], l2W[j * 2 + c], v);
        out[g * 2 + c] = v;
    }
}

// ---------------- launch ----------------
extern "C" void kernel_launch(void* const* d_in, const int* in_sizes, int n_in,
                              void* d_out, int out_size) {
    const float* x     = (const float*)d_in[0];
    const int*   esrc  = (const int*)d_in[1];
    const int*   edst  = (const int*)d_in[2];
    const float* ea    = (const float*)d_in[3];
    const int*   batch = (const int*)d_in[4];

    const float* c0W1 = (const float*)d_in[5];
    const float* c0b1 = (const float*)d_in[6];
    const float* c0W2 = (const float*)d_in[7];
    const float* c0b2 = (const float*)d_in[8];
    const float* c0rt = (const float*)d_in[9];
    const float* c0bs = (const float*)d_in[10];
    const float* bn0g = (const float*)d_in[11];
    const float* bn0b = (const float*)d_in[12];
    const float* bn0m = (const float*)d_in[13];
    const float* bn0v = (const float*)d_in[14];

    const float* c1W1 = (const float*)d_in[15];
    const float* c1b1 = (const float*)d_in[16];
    const float* c1W2 = (const float*)d_in[17];
    const float* c1b2 = (const float*)d_in[18];
    const float* c1rt = (const float*)d_in[19];
    const float* c1bs = (const float*)d_in[20];
    const float* bn1g = (const float*)d_in[21];
    const float* bn1b = (const float*)d_in[22];
    const float* bn1m = (const float*)d_in[23];
    const float* bn1v = (const float*)d_in[24];

    const float* l1W = (const float*)d_in[25];
    const float* l1b = (const float*)d_in[26];
    const float* l2W = (const float*)d_in[27];
    const float* l2b = (const float*)d_in[28];

    float* out = (float*)d_out;

    void* px1 = nullptr;
    cudaGetSymbolAddress(&px1, g_x1);
    float* x1 = (float*)px1;

    dim3 zg(8, N_NODES / 32);

    // launch index:                                  (ncu -s 5 lands on #5)
    k_zero_agg_pool<<<(N_NODES * DIM + 255) / 256, 256>>>();       // 0
    k_zgemm<<<zg, 256>>>(x, c0W2, c0b2);                           // 1
    k_edge_fused<<<N_EDGES / EPB, 256>>>(ea, c0W1, c0b1, esrc, edst); // 2
    k_node_update<false><<<N_NODES / 8, 256>>>(x, c0rt, c0bs, bn0g, bn0b,
                                               bn0m, bn0v, x1, nullptr); // 3
    k_zero_agg<<<(N_NODES * DIM + 255) / 256, 256>>>();            // 4
    k_zgemm<<<zg, 256>>>(x1, c1W2, c1b2);                          // 5 <- profiled
    k_edge_fused<<<N_EDGES / EPB, 256>>>(ea, c1W1, c1b1, esrc, edst);
    k_node_update<true><<<N_NODES / 8, 256>>>(x1, c1rt, c1bs, bn1g, bn1b,
                                              bn1m, bn1v, nullptr, batch);

    // ---- head ----
    k_head<<<1, NG>>>(l1W, l1b, l2W, l2b, out);
}

// round 11
// speedup vs baseline: 1.2588x; 1.2588x over previous
#include <cuda_runtime.h>
#include <cuda_fp16.h>
#include <cstdint>

#define N_NODES 20000
#define N_EDGES 160000
#define DIM 32
#define EFD 95
#define EH 64
#define NG 64
#define ZCOLS 2048      // EH * DIM
#define BN_EPS 1e-5f
#define EPB 64          // edges per fused block
#define EAS 98          // padded ea row stride (halves)
#define HSS 68          // padded hs row stride (floats)

// ---------------- scratch (device globals) ----------------
__device__ __align__(16) __half g_Zh[(size_t)N_NODES * ZCOLS];  // 82 MB  [n][kb][o][r]
__device__ float  g_Zb[N_NODES * DIM];
__device__ float  g_agg[N_NODES * DIM];
__device__ float  g_x1[N_NODES * DIM];
__device__ float  g_pool[NG * DIM];

// ---------------- zero kernels ----------------
__global__ void k_zero_agg_pool() {
    int i = blockIdx.x * blockDim.x + threadIdx.x;
    if (i < NG * DIM) g_pool[i] = 0.f;
    if (i < N_NODES * DIM) g_agg[i] = 0.f;
}
__global__ void k_zero_agg() {
    int i = blockIdx.x * blockDim.x + threadIdx.x;
    if (i < N_NODES * DIM) g_agg[i] = 0.f;
}

// ---------------- K2: Zh[n][kb][o][r] (round-3 core, known 72us) ----------
__global__ void __launch_bounds__(256) k_zgemm(const float* __restrict__ X,
                                               const float* __restrict__ W2) {
    __shared__ float Xs[32 * DIM];
    __shared__ float Bs[8 * 32 * 32];
    int t = threadIdx.x;
    int kb = blockIdx.x;
    int n0 = blockIdx.y * 32;

    for (int i = t; i < 32 * DIM; i += 256)
        Xs[i] = X[(size_t)n0 * DIM + i];
    const float* w2src = W2 + (size_t)kb * 8192;
#pragma unroll
    for (int i = 0; i < 8192; i += 256)
        Bs[i + t] = w2src[i + t];
    __syncthreads();

    int o = t & 31, trow = t >> 5;
    float acc[4][8] = {};
#pragma unroll
    for (int i = 0; i < DIM; i++) {
        float b[8];
#pragma unroll
        for (int r = 0; r < 8; r++) b[r] = Bs[r * 1024 + i * 32 + o];
#pragma unroll
        for (int rr = 0; rr < 4; rr++) {
            float a = Xs[(trow * 4 + rr) * DIM + i];
#pragma unroll
            for (int r = 0; r < 8; r++)
                acc[rr][r] = fmaf(a, b[r], acc[rr][r]);
        }
    }
#pragma unroll
    for (int rr = 0; rr < 4; rr++) {
        int n = n0 + trow * 4 + rr;
        __half2 p0 = __floats2half2_rn(acc[rr][0], acc[rr][1]);
        __half2 p1 = __floats2half2_rn(acc[rr][2], acc[rr][3]);
        __half2 p2 = __floats2half2_rn(acc[rr][4], acc[rr][5]);
        __half2 p3 = __floats2half2_rn(acc[rr][6], acc[rr][7]);
        uint4 pk = make_uint4(*(uint32_t*)&p0, *(uint32_t*)&p1,
                              *(uint32_t*)&p2, *(uint32_t*)&p3);
        *(uint4*)&g_Zh[(size_t)n * ZCOLS + kb * 256 + o * 8] = pk;
    }
}

// ---------------- K2b: Zb[n,o] = sum_i X[n,i] * b2[i*32+o] ----------------
__global__ void k_zb(const float* __restrict__ X, const float* __restrict__ b2) {
    __shared__ float Bs[DIM * DIM];
    int t = threadIdx.x;
    for (int i = t; i < DIM * DIM; i += 256) Bs[i] = b2[i];
    __syncthreads();
    int n = blockIdx.x * 8 + (t >> 5);
    int o = t & 31;
    const float* xr = X + (size_t)n * DIM;
    float v = 0.f;
#pragma unroll
    for (int i = 0; i < DIM; i++) v = fmaf(xr[i], Bs[i * DIM + o], v);
    g_Zb[n * DIM + o] = v;
}

// ---------------- K3: FUSED edge MLP + scatter ----------------
// Phase 1: W1 in fp32 smem (broadcast LDS.128, zero cvts); ea in fp16 smem.
// Phase 2: unchanged from round 8.
__global__ void __launch_bounds__(256) k_edge_fused(const float* __restrict__ ea,
                                                    const float* __restrict__ W1,
                                                    const float* __restrict__ b1,
                                                    const int* __restrict__ esrc,
                                                    const int* __restrict__ edst) {
    __shared__ float  W1s[EFD * EH];        // 24320 B, [k][j] fp32
    __shared__ __half eash[EPB * EAS];      // 12544 B, [el][k], stride 98
    __shared__ float  hs[EPB][HSS];         // 17408 B   (total ~54 KB)
    int t = threadIdx.x;
    int e0 = blockIdx.x * EPB;

    for (int i = t; i < EFD * EH; i += 256) W1s[i] = W1[i];
    for (int i = t; i < EPB * EFD; i += 256) {
        int el = i / EFD, k = i - el * EFD;
        eash[el * EAS + k] = __float2half(ea[(size_t)e0 * EFD + i]);
    }
    __syncthreads();

    int lane = t & 31;
    int jg = t >> 5;
    float bj[8];
#pragma unroll
    for (int j = 0; j < 8; j++) bj[j] = b1[jg * 8 + j];

#pragma unroll
    for (int pass = 0; pass < 2; pass++) {
        int el = pass * 32 + lane;
        float acc[8];
#pragma unroll
        for (int j = 0; j < 8; j++) acc[j] = bj[j];

        const __half* ear = &eash[el * EAS];
        const float* wr = &W1s[jg * 8];
#pragma unroll 2
        for (int k = 0; k < EFD - 1; k += 2) {
            __half2 ah = *(const __half2*)(ear + k);        // conflict-free LDS
            float2 af = __half22float2(ah);
            float4 w00 = *(const float4*)(wr + k * EH);         // broadcast
            float4 w01 = *(const float4*)(wr + k * EH + 4);     // broadcast
            float4 w10 = *(const float4*)(wr + (k + 1) * EH);   // broadcast
            float4 w11 = *(const float4*)(wr + (k + 1) * EH + 4);
            acc[0] = fmaf(af.x, w00.x, acc[0]);
            acc[1] = fmaf(af.x, w00.y, acc[1]);
            acc[2] = fmaf(af.x, w00.z, acc[2]);
            acc[3] = fmaf(af.x, w00.w, acc[3]);
            acc[4] = fmaf(af.x, w01.x, acc[4]);
            acc[5] = fmaf(af.x, w01.y, acc[5]);
            acc[6] = fmaf(af.x, w01.z, acc[6]);
            acc[7] = fmaf(af.x, w01.w, acc[7]);
            acc[0] = fmaf(af.y, w10.x, acc[0]);
            acc[1] = fmaf(af.y, w10.y, acc[1]);
            acc[2] = fmaf(af.y, w10.z, acc[2]);
            acc[3] = fmaf(af.y, w10.w, acc[3]);
            acc[4] = fmaf(af.y, w11.x, acc[4]);
            acc[5] = fmaf(af.y, w11.y, acc[5]);
            acc[6] = fmaf(af.y, w11.z, acc[6]);
            acc[7] = fmaf(af.y, w11.w, acc[7]);
        }
        {   // tail k = 94
            int k = EFD - 1;
            float a = __half2float(ear[k]);
            float4 w00 = *(const float4*)(wr + k * EH);
            float4 w01 = *(const float4*)(wr + k * EH + 4);
            acc[0] = fmaf(a, w00.x, acc[0]);
            acc[1] = fmaf(a, w00.y, acc[1]);
            acc[2] = fmaf(a, w00.z, acc[2]);
            acc[3] = fmaf(a, w00.w, acc[3]);
            acc[4] = fmaf(a, w01.x, acc[4]);
            acc[5] = fmaf(a, w01.y, acc[5]);
            acc[6] = fmaf(a, w01.z, acc[6]);
            acc[7] = fmaf(a, w01.w, acc[7]);
        }
        float4 r0 = make_float4(fmaxf(acc[0], 0.f), fmaxf(acc[1], 0.f),
                                fmaxf(acc[2], 0.f), fmaxf(acc[3], 0.f));
        float4 r1 = make_float4(fmaxf(acc[4], 0.f), fmaxf(acc[5], 0.f),
                                fmaxf(acc[6], 0.f), fmaxf(acc[7], 0.f));
        *(float4*)&hs[el][jg * 8] = r0;
        *(float4*)&hs[el][jg * 8 + 4] = r1;
    }
    __syncthreads();

    int wid = t >> 5;
#pragma unroll
    for (int rnd = 0; rnd < 8; rnd++) {
        int eloc = rnd * 8 + wid;
        int e = e0 + eloc;
        int s = esrc[e], d = edst[e];
        const __half* zr = g_Zh + (size_t)s * ZCOLS + lane * 8;
        const float* hr = hs[eloc];
        float msg0 = g_Zb[s * DIM + lane];
        float msg1 = 0.f;
#pragma unroll
        for (int kb = 0; kb < 8; kb += 2) {
            uint4 v0 = __ldg((const uint4*)(zr + kb * 256));
            uint4 v1 = __ldg((const uint4*)(zr + (kb + 1) * 256));
            float4 h0 = *(const float4*)&hr[kb * 8];
            float4 h1 = *(const float4*)&hr[kb * 8 + 4];
            float4 h2 = *(const float4*)&hr[kb * 8 + 8];
            float4 h3 = *(const float4*)&hr[kb * 8 + 12];
            float2 a0 = __half22float2(*(__half2*)&v0.x);
            float2 a1 = __half22float2(*(__half2*)&v0.y);
            float2 a2 = __half22float2(*(__half2*)&v0.z);
            float2 a3 = __half22float2(*(__half2*)&v0.w);
            float2 b0 = __half22float2(*(__half2*)&v1.x);
            float2 b1 = __half22float2(*(__half2*)&v1.y);
            float2 b2 = __half22float2(*(__half2*)&v1.z);
            float2 b3 = __half22float2(*(__half2*)&v1.w);
            msg0 = fmaf(h0.x, a0.x, msg0);
            msg1 = fmaf(h0.y, a0.y, msg1);
            msg0 = fmaf(h0.z, a1.x, msg0);
            msg1 = fmaf(h0.w, a1.y, msg1);
            msg0 = fmaf(h1.x, a2.x, msg0);
            msg1 = fmaf(h1.y, a2.y, msg1);
            msg0 = fmaf(h1.z, a3.x, msg0);
            msg1 = fmaf(h1.w, a3.y, msg1);
            msg0 = fmaf(h2.x, b0.x, msg0);
            msg1 = fmaf(h2.y, b0.y, msg1);
            msg0 = fmaf(h2.z, b1.x, msg0);
            msg1 = fmaf(h2.w, b1.y, msg1);
            msg0 = fmaf(h3.x, b2.x, msg0);
            msg1 = fmaf(h3.y, b2.y, msg1);
            msg0 = fmaf(h3.z, b3.x, msg0);
            msg1 = fmaf(h3.w, b3.y, msg1);
        }
        atomicAdd(&g_agg[d * DIM + lane], msg0 + msg1);
    }
}

// ---------------- K4: node update ----------------
template <bool POOL>
__global__ void k_node_update(const float* __restrict__ xin,
                              const float* __restrict__ root,
                              const float* __restrict__ bias,
                              const float* __restrict__ bng,
                              const float* __restrict__ bnb,
                              const float* __restrict__ bnrm,
                              const float* __restrict__ bnrv,
                              float* __restrict__ xout,
                              const int* __restrict__ batch) {
    __shared__ float Rs[DIM * DIM];
    int t = threadIdx.x;
    for (int i = t; i < DIM * DIM; i += 256) Rs[i] = root[i];
    __syncthreads();
    int n = blockIdx.x * 8 + (t >> 5);
    int o = t & 31;
    const float* xr = xin + (size_t)n * DIM;
    float v = g_agg[n * DIM + o] + bias[o];
#pragma unroll
    for (int i = 0; i < DIM; i++) v = fmaf(xr[i], Rs[i * DIM + o], v);
    v = (v - bnrm[o]) * rsqrtf(bnrv[o] + BN_EPS) * bng[o] + bnb[o];
    v = fmaxf(v, 0.f);
    if (POOL) {
        int b = batch[n];
        atomicMax((int*)&g_pool[b * DIM + o], __float_as_int(v));
    } else {
        xout[n * DIM + o] = v;
    }
}

// ---------------- K6: head ----------------
__global__ void k_head(const float* __restrict__ l1W, const float* __restrict__ l1b,
                       const float* __restrict__ l2W, const float* __restrict__ l2b,
                       float* __restrict__ out) {
    int g = threadIdx.x;
    const float* pr = &g_pool[g * DIM];
    float tbuf[DIM];
#pragma unroll
    for (int j = 0; j < DIM; j++) {
        float v = l1b[j];
#pragma unroll
        for (int i = 0; i < DIM; i++) v = fmaf(pr[i], l1W[i * DIM + j], v);
        tbuf[j] = fmaxf(v, 0.f);
    }
#pragma unroll
    for (int c = 0; c < 2; c++) {
        float v = l2b[c];
#pragma unroll
        for (int j = 0; j < DIM; j++) v = fmaf(tbuf[j], l2W[j * 2 + c], v);
        out[g * 2 + c] = v;
    }
}

// ---------------- launch (round-8 order) ----------------
extern "C" void kernel_launch(void* const* d_in, const int* in_sizes, int n_in,
                              void* d_out, int out_size) {
    const float* x     = (const float*)d_in[0];
    const int*   esrc  = (const int*)d_in[1];
    const int*   edst  = (const int*)d_in[2];
    const float* ea    = (const float*)d_in[3];
    const int*   batch = (const int*)d_in[4];

    const float* c0W1 = (const float*)d_in[5];
    const float* c0b1 = (const float*)d_in[6];
    const float* c0W2 = (const float*)d_in[7];
    const float* c0b2 = (const float*)d_in[8];
    const float* c0rt = (const float*)d_in[9];
    const float* c0bs = (const float*)d_in[10];
    const float* bn0g = (const float*)d_in[11];
    const float* bn0b = (const float*)d_in[12];
    const float* bn0m = (const float*)d_in[13];
    const float* bn0v = (const float*)d_in[14];

    const float* c1W1 = (const float*)d_in[15];
    const float* c1b1 = (const float*)d_in[16];
    const float* c1W2 = (const float*)d_in[17];
    const float* c1b2 = (const float*)d_in[18];
    const float* c1rt = (const float*)d_in[19];
    const float* c1bs = (const float*)d_in[20];
    const float* bn1g = (const float*)d_in[21];
    const float* bn1b = (const float*)d_in[22];
    const float* bn1m = (const float*)d_in[23];
    const float* bn1v = (const float*)d_in[24];

    const float* l1W = (const float*)d_in[25];
    const float* l1b = (const float*)d_in[26];
    const float* l2W = (const float*)d_in[27];
    const float* l2b = (const float*)d_in[28];

    float* out = (float*)d_out;

    void* px1 = nullptr;
    cudaGetSymbolAddress(&px1, g_x1);
    float* x1 = (float*)px1;

    dim3 zg(8, N_NODES / 32);

    // ---- conv0 ----
    k_zero_agg_pool<<<(N_NODES * DIM + 255) / 256, 256>>>();
    k_zgemm<<<zg, 256>>>(x, c0W2);
    k_zb<<<N_NODES / 8, 256>>>(x, c0b2);
    k_edge_fused<<<N_EDGES / EPB, 256>>>(ea, c0W1, c0b1, esrc, edst);
    k_node_update<false><<<N_NODES / 8, 256>>>(x, c0rt, c0bs, bn0g, bn0b,
                                               bn0m, bn0v, x1, nullptr);

    // ---- conv1 ----
    k_zero_agg<<<(N_NODES * DIM + 255) / 256, 256>>>();
    k_zgemm<<<zg, 256>>>(x1, c1W2);
    k_zb<<<N_NODES / 8, 256>>>(x1, c1b2);
    k_edge_fused<<<N_EDGES / EPB, 256>>>(ea, c1W1, c1b1, esrc, edst);
    k_node_update<true><<<N_NODES / 8, 256>>>(x1, c1rt, c1bs, bn1g, bn1b,
                                              bn1m, bn1v, nullptr, batch);

    // ---- head ----
    k_head<<<1, NG>>>(l1W, l1b, l2W, l2b, out);
}